// round 13
// baseline (speedup 1.0000x reference)
#include <cuda_runtime.h>
#include <cuda_bf16.h>
#include <cstddef>

// ---------------------------------------------------------------------------
// DRNN: 2-layer SimpleRNN (tanh), B=512, T=512, D=64, H=100.
//   h1_t = tanh(x_t @ W1x + h1_{t-1} @ W1h + b1)
//   h2_t = tanh(h1_t @ W2x + h2_{t-1} @ W2h + b2)
//   out  = h2_T @ Wo + bo
// d_out: out[512] | h1_T[512*100] | h2_T[512*100]
//
// R8 analysis: rnn stuck at ~2700 cyc/step; stall time = 4-barrier critical
// path + scr STS->bar->LDS chains. Fix: half-split moved INSIDE the warp
// (hf = lane>>4), so the cross-half exchange is 2 shfl.xor(16) per layer and
// the step needs only 2 __syncthreads. Everything else keeps the measured-
// best R4 structure (weights in regs, FFMA2, double-buffered h).
// ---------------------------------------------------------------------------

#define T_STEPS 512
#define BATCH   512
#define IN_DIM  64
#define H       100
#define HP      104   // xw scratch stride
#define JPH     25    // j-pairs per half (half covers 50 j values)

typedef unsigned long long u64t;

// scratch: [T][B][HP] floats = 109 MB (zero-init; pad cols 100..103 unread)
__device__ float g_xw[(size_t)T_STEPS * BATCH * HP];

__device__ __forceinline__ void ffma2(u64t& d, u64t a, u64t b) {
    asm("fma.rn.f32x2 %0, %1, %2, %0;" : "+l"(d) : "l"(a), "l"(b));
}
__device__ __forceinline__ u64t pack2(float lo, float hi) {
    u64t r;
    asm("mov.b64 %0, {%1, %2};" : "=l"(r) : "f"(lo), "f"(hi));
    return r;
}
__device__ __forceinline__ void unpack2(float& lo, float& hi, u64t v) {
    asm("mov.b64 {%0, %1}, %2;" : "=f"(lo), "=f"(hi) : "l"(v));
}
__device__ __forceinline__ float sum2(u64t v) {
    float lo, hi;
    unpack2(lo, hi, v);
    return lo + hi;
}
// tanh via exp(2x): 2 MUFU + few FMA, abs err ~1e-7 with clamp (validated).
__device__ __forceinline__ float fast_tanh(float x) {
    x = fminf(fmaxf(x, -15.0f), 15.0f);
    float e;
    asm("ex2.approx.f32 %0, %1;" : "=f"(e) : "f"(x * 2.885390081777927f));
    float r;
    asm("rcp.approx.f32 %0, %1;" : "=f"(r) : "f"(e + 1.0f));
    return (e - 1.0f) * r;
}

// ---------------------------------------------------------------------------
// Kernel 1: xw[t][b][u] = b1[u] + x[b][t][:] @ W1x[:][u]
// ---------------------------------------------------------------------------
#define PC_THREADS 200

__global__ void __launch_bounds__(PC_THREADS) precompute_xw_kernel(
    const float* __restrict__ x,     // [B][T][D]
    const float* __restrict__ W1x,   // [D][H]
    const float* __restrict__ b1)    // [H]
{
    __shared__ __align__(16) float sW[IN_DIM * H];   // [d][u]
    __shared__ __align__(16) float sxT[IN_DIM * 64]; // [d][row]

    const int t   = blockIdx.x;
    const int b0  = blockIdx.y * 64;
    const int tid = threadIdx.x;

    for (int i = tid; i < IN_DIM * H; i += PC_THREADS) sW[i] = W1x[i];
    for (int i = tid; i < 64 * IN_DIM; i += PC_THREADS) {
        int bl = i >> 6, d = i & 63;
        sxT[d * 64 + bl] =
            x[(size_t)(b0 + bl) * (T_STEPS * IN_DIM) + (size_t)t * IN_DIM + d];
    }
    __syncthreads();

    const int ug = tid >> 3;     // 0..24 -> u = 4*ug
    const int ro = tid & 7;      // rows ro*8 .. ro*8+7
    const int u  = ug * 4;

    u64t acc[4][4];
    #pragma unroll
    for (int ul = 0; ul < 4; ul++) {
        float b = b1[u + ul];
        #pragma unroll
        for (int rp = 0; rp < 4; rp++) acc[ul][rp] = pack2(b, b);
    }

    #pragma unroll 8
    for (int d = 0; d < IN_DIM; d++) {
        ulonglong2 x01 = *(const ulonglong2*)&sxT[d * 64 + ro * 8];
        ulonglong2 x23 = *(const ulonglong2*)&sxT[d * 64 + ro * 8 + 4];
        float4 w = *(const float4*)&sW[d * H + u];
        u64t w0 = pack2(w.x, w.x);
        u64t w1 = pack2(w.y, w.y);
        u64t w2 = pack2(w.z, w.z);
        u64t w3 = pack2(w.w, w.w);
        ffma2(acc[0][0], x01.x, w0); ffma2(acc[0][1], x01.y, w0);
        ffma2(acc[0][2], x23.x, w0); ffma2(acc[0][3], x23.y, w0);
        ffma2(acc[1][0], x01.x, w1); ffma2(acc[1][1], x01.y, w1);
        ffma2(acc[1][2], x23.x, w1); ffma2(acc[1][3], x23.y, w1);
        ffma2(acc[2][0], x01.x, w2); ffma2(acc[2][1], x01.y, w2);
        ffma2(acc[2][2], x23.x, w2); ffma2(acc[2][3], x23.y, w2);
        ffma2(acc[3][0], x01.x, w3); ffma2(acc[3][1], x01.y, w3);
        ffma2(acc[3][2], x23.x, w3); ffma2(acc[3][3], x23.y, w3);
    }

    #pragma unroll
    for (int rp = 0; rp < 4; rp++) {
        float l0, h0, l1, h1, l2, h2, l3, h3;
        unpack2(l0, h0, acc[0][rp]);
        unpack2(l1, h1, acc[1][rp]);
        unpack2(l2, h2, acc[2][rp]);
        unpack2(l3, h3, acc[3][rp]);
        int r0 = ro * 8 + rp * 2;
        size_t base = (size_t)t * (BATCH * HP) + (size_t)(b0 + r0) * HP + u;
        *(float4*)&g_xw[base]      = make_float4(l0, l1, l2, l3);
        *(float4*)&g_xw[base + HP] = make_float4(h0, h1, h2, h3);
    }
}

// ---------------------------------------------------------------------------
// Kernel 2: recurrence. 128 blocks x 4 rows, 256 threads (8 warps).
//   u  = warp*16 + (lane & 15)   (0..127; active < 100)
//   hf = lane >> 4               (j-range [hf*50, hf*50+50))
// Cross-half exchange: shfl.xor(16) — no barrier. 2 __syncthreads/step.
// Thread finalizes rows 2hf, 2hf+1 for its unit (xw/bias added post-shfl).
// ---------------------------------------------------------------------------
#define SM_H1  0      // [2][400]
#define SM_H2  800    // [2][400]
#define SM_WO  1600   // [128]
#define SM_FLOATS 1728

__global__ void __launch_bounds__(256, 1) rnn_kernel(
    const float* __restrict__ W1h,  // [H][H]
    const float* __restrict__ W2x,  // [H][H]
    const float* __restrict__ W2h,  // [H][H]
    const float* __restrict__ b2,   // [H]
    const float* __restrict__ Wo,   // [H][1]
    const float* __restrict__ bo,   // [1]
    float* __restrict__ out)        // [512 + 51200 + 51200]
{
    __shared__ __align__(16) float sm[SM_FLOATS];
    float* sh1 = sm + SM_H1;
    float* sh2 = sm + SM_H2;
    float* sWo = sm + SM_WO;

    const int tid  = threadIdx.x;
    const int lane = tid & 31;
    const int wid  = tid >> 5;            // 0..7
    const int hf   = lane >> 4;           // 0 or 1 (within warp!)
    const int u    = wid * 16 + (lane & 15);   // 0..127
    const int b0   = blockIdx.x * 4;
    const bool act = (u < H);

    // ---- weight slices into registers (packed f32x2 over j-pairs) ----
    u64t w1p[JPH], wxp[JPH], whp[JPH];
    #pragma unroll
    for (int jp = 0; jp < JPH; jp++) {
        int j = hf * 50 + 2 * jp;
        float a0 = 0.f, a1 = 0.f, x0 = 0.f, x1 = 0.f, c0 = 0.f, c1 = 0.f;
        if (act) {
            a0 = W1h[j * H + u]; a1 = W1h[(j + 1) * H + u];
            x0 = W2x[j * H + u]; x1 = W2x[(j + 1) * H + u];
            c0 = W2h[j * H + u]; c1 = W2h[(j + 1) * H + u];
        }
        w1p[jp] = pack2(a0, a1);
        wxp[jp] = pack2(x0, x1);
        whp[jp] = pack2(c0, c1);
    }
    const float bias = act ? b2[u] : 0.0f;
    if (tid < H) sWo[tid] = Wo[tid];
    for (int i = tid; i < 1600; i += 256) sm[i] = 0.0f;  // zero both h bufs
    __syncthreads();

    const int hoff = hf * 200;                 // my half's j-offset in h buf
    // my h store positions: rows 2hf, 2hf+1 for unit u
    const int hst0 = (u >> 1) * 8 + (2 * hf) * 2 + (u & 1);
    const int hst1 = hst0 + 2;

    // xw pointers: rows 2hf and 2hf+1 for unit u
    const float* xwp = g_xw + (size_t)(b0 + 2 * hf) * HP + u;
    float xwA = act ? xwp[0]  : 0.f;           // row 2hf
    float xwB = act ? xwp[HP] : 0.f;           // row 2hf+1

    for (int t = 0; t < T_STEPS; t++) {
        const int rb = (t & 1) * 400;
        const int wb = 400 - rb;
        const float* h1r = sh1 + rb + hoff;
        const float* h1n = sh1 + wb + hoff;    // read in layer 2 (after bar)
        const float* h2r = sh2 + rb + hoff;

        // software-pipelined prefetch of next timestep's xw
        float nxA = 0.f, nxB = 0.f;
        if (act && (t + 1 < T_STEPS)) {
            const float* p = xwp + (size_t)(t + 1) * (BATCH * HP);
            nxA = p[0];
            nxB = p[HP];
        }

        // ---- layer 1 partials over my half of j, rows 0..3 ----
        u64t a0 = 0, a1 = 0, a2 = 0, a3 = 0;
        #pragma unroll
        for (int jp = 0; jp < JPH; jp++) {
            ulonglong2 q01 = *(const ulonglong2*)&h1r[jp * 8];      // rows 0,1
            ulonglong2 q23 = *(const ulonglong2*)&h1r[jp * 8 + 4];  // rows 2,3
            ffma2(a0, q01.x, w1p[jp]);
            ffma2(a1, q01.y, w1p[jp]);
            ffma2(a2, q23.x, w1p[jp]);
            ffma2(a3, q23.y, w1p[jp]);
        }
        {
            float s0 = sum2(a0), s1 = sum2(a1), s2 = sum2(a2), s3 = sum2(a3);
            // send the rows I don't keep; hf0 keeps 0,1 / hf1 keeps 2,3
            float send0 = hf ? s0 : s2;
            float send1 = hf ? s1 : s3;
            float r0 = __shfl_xor_sync(0xffffffffu, send0, 16);
            float r1 = __shfl_xor_sync(0xffffffffu, send1, 16);
            float k0 = (hf ? s2 : s0) + r0 + xwA;   // row 2hf
            float k1 = (hf ? s3 : s1) + r1 + xwB;   // row 2hf+1
            k0 = fast_tanh(k0);
            k1 = fast_tanh(k1);
            if (act) {
                sh1[wb + hst0] = k0;
                sh1[wb + hst1] = k1;
            }
        }
        __syncthreads();   // h1_new visible to all warps

        // ---- layer 2 partials: h1_new @ W2x + h2_old @ W2h ----
        u64t c0 = 0, c1 = 0, c2 = 0, c3 = 0;
        #pragma unroll
        for (int jp = 0; jp < JPH; jp++) {
            ulonglong2 p01 = *(const ulonglong2*)&h1n[jp * 8];
            ulonglong2 p23 = *(const ulonglong2*)&h1n[jp * 8 + 4];
            ulonglong2 q01 = *(const ulonglong2*)&h2r[jp * 8];
            ulonglong2 q23 = *(const ulonglong2*)&h2r[jp * 8 + 4];
            ffma2(c0, p01.x, wxp[jp]); ffma2(c0, q01.x, whp[jp]);
            ffma2(c1, p01.y, wxp[jp]); ffma2(c1, q01.y, whp[jp]);
            ffma2(c2, p23.x, wxp[jp]); ffma2(c2, q23.x, whp[jp]);
            ffma2(c3, p23.y, wxp[jp]); ffma2(c3, q23.y, whp[jp]);
        }
        {
            float s0 = sum2(c0), s1 = sum2(c1), s2 = sum2(c2), s3 = sum2(c3);
            float send0 = hf ? s0 : s2;
            float send1 = hf ? s1 : s3;
            float r0 = __shfl_xor_sync(0xffffffffu, send0, 16);
            float r1 = __shfl_xor_sync(0xffffffffu, send1, 16);
            float k0 = (hf ? s2 : s0) + r0 + bias;
            float k1 = (hf ? s3 : s1) + r1 + bias;
            k0 = fast_tanh(k0);
            k1 = fast_tanh(k1);
            if (act) {
                sh2[wb + hst0] = k0;
                sh2[wb + hst1] = k1;
            }
        }
        __syncthreads();   // h2_new visible; old buffers free next step

        xwA = nxA; xwB = nxB;
    }

    // ---- epilogue: final state in buffer 0 (T=512 even) ----
    for (int i = tid; i < 4 * H; i += 256) {
        int r = i / H;
        int uu = i - r * H;
        int pos = (uu >> 1) * 8 + r * 2 + (uu & 1);
        out[512 + (size_t)(b0 + r) * H + uu]         = sh1[pos];
        out[512 + 51200 + (size_t)(b0 + r) * H + uu] = sh2[pos];
    }
    if (tid < 4) {
        float s = bo[0];
        for (int j = 0; j < H; j++)
            s += sh2[(j >> 1) * 8 + tid * 2 + (j & 1)] * sWo[j];
        out[b0 + tid] = s;
    }
}

// ---------------------------------------------------------------------------
extern "C" void kernel_launch(void* const* d_in, const int* in_sizes, int n_in,
                              void* d_out, int out_size)
{
    const float* x   = (const float*)d_in[0];
    const float* W1x = (const float*)d_in[1];
    const float* W1h = (const float*)d_in[2];
    const float* b1  = (const float*)d_in[3];
    const float* W2x = (const float*)d_in[4];
    const float* W2h = (const float*)d_in[5];
    const float* b2  = (const float*)d_in[6];
    const float* Wo  = (const float*)d_in[7];
    const float* bo  = (const float*)d_in[8];
    float* out = (float*)d_out;

    precompute_xw_kernel<<<dim3(T_STEPS, BATCH / 64), PC_THREADS>>>(x, W1x, b1);
    rnn_kernel<<<BATCH / 4, 256>>>(W1h, W2x, W2h, b2, Wo, bo, out);
}